// round 12
// baseline (speedup 1.0000x reference)
#include <cuda_runtime.h>
#include <cuda_bf16.h>
#include <cstdint>
#include <math.h>

// Problem constants
#define BD 64                 // batch
#define NP 576                // patches per image (24*24)
#define DD 768                // hidden = 3*16*16
#define LL 1024               // latents
#define MROWS (BD * NP)       // 36864 flattened (b, patch) rows

// ---------------------------------------------------------------------------
// Scratch (__device__ globals: allocation-free per harness rules)
// ---------------------------------------------------------------------------
__device__ __align__(16) __nv_bfloat16 g_patchb[(size_t)MROWS * DD]; // conv out bf16
__device__ __align__(16) __nv_bfloat16 g_xim [(size_t)MROWS * DD];   // im2col(x) bf16
__device__ __align__(16) __nv_bfloat16 g_pnb [(size_t)MROWS * DD];   // normalized patches bf16
__device__ __align__(16) __nv_bfloat16 g_lnb [(size_t)LL * DD];      // normalized latent bf16
__device__ __align__(16) __nv_bfloat16 g_wb  [(size_t)DD * DD];      // conv weights bf16
__device__ float g_far[BD];
__device__ float g_close[BD];

// ---------------------------------------------------------------------------
// Helpers
// ---------------------------------------------------------------------------
__device__ __forceinline__ uint32_t smem_to_u32(const void* smem_ptr) {
    uint32_t addr;
    asm("{ .reg .u64 tmp; cvta.to.shared.u64 tmp, %1; cvt.u32.u64 %0, tmp; }"
        : "=r"(addr) : "l"(smem_ptr));
    return addr;
}

__device__ __forceinline__ float warpSum(float v) {
#pragma unroll
    for (int o = 16; o; o >>= 1) v += __shfl_xor_sync(0xffffffffu, v, o);
    return v;
}

__device__ __forceinline__ void ldsm_x4(uint32_t* d, uint32_t addr) {
    asm volatile("ldmatrix.sync.aligned.m8n8.x4.shared.b16 {%0,%1,%2,%3}, [%4];"
                 : "=r"(d[0]), "=r"(d[1]), "=r"(d[2]), "=r"(d[3]) : "r"(addr));
}

__device__ __forceinline__ void mma_bf16(float* c, const uint32_t* a,
                                         uint32_t b0, uint32_t b1) {
    asm volatile(
        "mma.sync.aligned.m16n8k16.row.col.f32.bf16.bf16.f32 "
        "{%0,%1,%2,%3}, {%4,%5,%6,%7}, {%8,%9}, {%0,%1,%2,%3};"
        : "+f"(c[0]), "+f"(c[1]), "+f"(c[2]), "+f"(c[3])
        : "r"(a[0]), "r"(a[1]), "r"(a[2]), "r"(a[3]), "r"(b0), "r"(b1));
}

__device__ __forceinline__ void cp16(uint32_t saddr, const void* gptr) {
    asm volatile("cp.async.cg.shared.global [%0], [%1], 16;" :: "r"(saddr), "l"(gptr));
}

#define CP_COMMIT() asm volatile("cp.async.commit_group;")

#define SWZ(off) ((off) ^ (((off) >> 3) & 0x70))

// ---------------------------------------------------------------------------
// Pre-pass kernels: bf16 conversions
// ---------------------------------------------------------------------------

// im2col + fp32->bf16: g_xim[(b*576+np)*768 + k], k = c*256 + rr*16 + cc
__global__ __launch_bounds__(256) void im2col_kernel(const float* __restrict__ x) {
    int s = blockIdx.x * 256 + threadIdx.x;
    int row = s / 48;
    int seg = s - row * 48;
    int b   = row / NP;
    int np  = row - b * NP;
    int ph  = np / 24, pw = np - ph * 24;
    int c   = seg >> 4, rr = seg & 15;
    const float4* src = (const float4*)(x + ((size_t)(b * 3 + c) * 384 + ph * 16 + rr) * 384 + pw * 16);
    float4 q0 = src[0], q1 = src[1], q2 = src[2], q3 = src[3];
    __align__(16) __nv_bfloat162 h[8];
    h[0] = __floats2bfloat162_rn(q0.x, q0.y); h[1] = __floats2bfloat162_rn(q0.z, q0.w);
    h[2] = __floats2bfloat162_rn(q1.x, q1.y); h[3] = __floats2bfloat162_rn(q1.z, q1.w);
    h[4] = __floats2bfloat162_rn(q2.x, q2.y); h[5] = __floats2bfloat162_rn(q2.z, q2.w);
    h[6] = __floats2bfloat162_rn(q3.x, q3.y); h[7] = __floats2bfloat162_rn(q3.z, q3.w);
    uint4* dst = (uint4*)(g_xim + (size_t)row * DD + seg * 16);
    dst[0] = ((const uint4*)h)[0];
    dst[1] = ((const uint4*)h)[1];
}

// conv weights fp32 -> bf16 (OIHW flattening == k order)
__global__ __launch_bounds__(256) void wconv_kernel(const float* __restrict__ w) {
    int i = blockIdx.x * 256 + threadIdx.x;   // 147456 float4s
    float4 q = ((const float4*)w)[i];
    __align__(8) __nv_bfloat162 h2[2] = {__floats2bfloat162_rn(q.x, q.y),
                                         __floats2bfloat162_rn(q.z, q.w)};
    ((uint2*)g_wb)[i] = *(const uint2*)h2;
}

// L2-normalize conv output rows (bf16 in, bf16 out). grid = MROWS, 256 thr.
__global__ __launch_bounds__(256) void norm_patch_kernel() {
    const __nv_bfloat16* p = g_patchb + (size_t)blockIdx.x * DD;
    __nv_bfloat16* o = g_pnb + (size_t)blockIdx.x * DD;
    const int tid = threadIdx.x;
    float v0 = __bfloat162float(p[tid]);
    float v1 = __bfloat162float(p[tid + 256]);
    float v2 = __bfloat162float(p[tid + 512]);
    float ss = v0 * v0 + v1 * v1 + v2 * v2;

    __shared__ float red[8];
    __shared__ float s_inv;
    float t = warpSum(ss);
    if ((tid & 31) == 0) red[tid >> 5] = t;
    __syncthreads();
    if (tid < 32) {
        float u = (tid < 8) ? red[tid] : 0.f;
        u = warpSum(u);
        if (tid == 0) s_inv = 1.0f / fmaxf(sqrtf(u), 1e-8f);
    }
    __syncthreads();
    const float inv = s_inv;
    o[tid]       = __float2bfloat16(v0 * inv);
    o[tid + 256] = __float2bfloat16(v1 * inv);
    o[tid + 512] = __float2bfloat16(v2 * inv);
}

// Normalize latent rows (fp32 in, bf16 out). grid = LL, 256 thr.
__global__ __launch_bounds__(256) void norm_latent_kernel(const float* __restrict__ latent) {
    const float* s = latent + (size_t)blockIdx.x * DD;
    __nv_bfloat16* d = g_lnb + (size_t)blockIdx.x * DD;
    const int tid = threadIdx.x;
    float v0 = s[tid], v1 = s[tid + 256], v2 = s[tid + 512];
    float ss = v0 * v0 + v1 * v1 + v2 * v2;

    __shared__ float red[8];
    __shared__ float s_inv;
    float t = warpSum(ss);
    if ((tid & 31) == 0) red[tid >> 5] = t;
    __syncthreads();
    if (tid < 32) {
        float u = (tid < 8) ? red[tid] : 0.f;
        u = warpSum(u);
        if (tid == 0) s_inv = 1.0f / fmaxf(sqrtf(u), 1e-8f);
    }
    __syncthreads();
    const float inv = s_inv;
    d[tid]       = __float2bfloat16(v0 * inv);
    d[tid + 256] = __float2bfloat16(v1 * inv);
    d[tid + 512] = __float2bfloat16(v2 * inv);
}

// ---------------------------------------------------------------------------
// bf16 HMMA GEMM: 128x128 block tile, BK=64, 2-stage cp.async double buffer.
// NEW: 4 warps (128 thr), warp tile 64x64 -> MMA:ldsm ratio 4.0 (was 2.67),
// 32 independent acc chains per warp. __launch_bounds__(128,2) -> 2 CTA/SM.
//   MODE 0: conv   A=g_xim (36864), B=g_wb (768)   -> g_patchb (bf16) + bias
//   MODE 1: far    A=B=g_pnb batch slice (576, clamp+mask) -> exp+reduce
//   MODE 2: close  A=g_lnb (1024),  B=g_pnb (36864) -> exp+reduce (batch split)
// ---------------------------------------------------------------------------
#define NCHUNK 12
#define TILE_B 16384
#define SMEM_DYN (4 * TILE_B)

template<int MODE>
__global__ __launch_bounds__(128, 2)
void mma_kernel(const float* __restrict__ bias) {
    if (MODE == 1 && blockIdx.y > blockIdx.x) return;  // symmetric: lower triangle

    extern __shared__ __align__(1024) unsigned char smem[];
    __shared__ float s_red[4];
    const uint32_t sbase = smem_to_u32(smem);
    const int tid = threadIdx.x, lane = tid & 31, wid = tid >> 5;
    const int warp_m = wid & 1, warp_n = wid >> 1;   // 2x2 grid of 64x64 tiles

    int m0, n0;
    const __nv_bfloat16 *Ap, *Bp;
    if (MODE == 0)      { m0 = blockIdx.x * 128; n0 = blockIdx.y * 128; Ap = g_xim; Bp = g_wb; }
    else if (MODE == 1) { m0 = blockIdx.x * 128; n0 = blockIdx.y * 128;
                          Ap = g_pnb + (size_t)blockIdx.z * NP * DD; Bp = Ap; }
    else                { m0 = blockIdx.y * 128; n0 = blockIdx.x * 128; Ap = g_lnb; Bp = g_pnb; }

    // Copy plan: each of 128 threads owns one 128-byte row of A and of B.
    int ra = m0 + tid, rb = n0 + tid;
    if (MODE == 1) {                        // clamp padded rows; masked later
        ra = ra < NP - 1 ? ra : NP - 1;
        rb = rb < NP - 1 ? rb : NP - 1;
    }
    const __nv_bfloat16* gA = Ap + (size_t)ra * DD;
    const __nv_bfloat16* gB = Bp + (size_t)rb * DD;
    uint32_t swrow[8];
#pragma unroll
    for (int cc = 0; cc < 8; ++cc)
        swrow[cc] = SWZ((uint32_t)(tid * 128 + cc * 16));

#define LOAD_CHUNK(ch, buf) do {                                        \
        uint32_t _sA = sbase + (uint32_t)(buf) * (2 * TILE_B);          \
        uint32_t _sB = _sA + TILE_B;                                    \
        _Pragma("unroll")                                               \
        for (int cc = 0; cc < 8; ++cc) {                                \
            cp16(_sA + swrow[cc], (const void*)(gA + (ch) * 64 + cc * 8)); \
            cp16(_sB + swrow[cc], (const void*)(gB + (ch) * 64 + cc * 8)); \
        }                                                               \
        CP_COMMIT();                                                    \
    } while (0)

    float acc[4][8][4] = {};   // [m-tile 16][n-octet 8][frag]

    // ldmatrix lane mappings
    const int arow = warp_m * 64 + (lane & 15);       // + mt*16
    const int ac16 = lane >> 4;                       // k 16B sub-chunk
    const int brow = warp_n * 64 + (lane & 7) + ((lane >> 4) << 3);  // + nt16*16
    const int bc16 = (lane >> 3) & 1;

    LOAD_CHUNK(0, 0);

    for (int ch = 0; ch < NCHUNK; ++ch) {
        const int buf = ch & 1;
        if (ch < NCHUNK - 1) {
            LOAD_CHUNK(ch + 1, buf ^ 1);
            asm volatile("cp.async.wait_group 1;");
        } else {
            asm volatile("cp.async.wait_group 0;");
        }
        __syncthreads();

        const uint32_t aT = sbase + (uint32_t)buf * (2 * TILE_B);
        const uint32_t bT = aT + TILE_B;
#pragma unroll
        for (int kk = 0; kk < 4; ++kk) {
            uint32_t af[4][4];
#pragma unroll
            for (int mt = 0; mt < 4; ++mt) {
                uint32_t off = (uint32_t)((arow + mt * 16) * 128 + (kk * 2 + ac16) * 16);
                ldsm_x4(af[mt], aT + SWZ(off));
            }
#pragma unroll
            for (int nt = 0; nt < 4; ++nt) {
                uint32_t bf4[4];
                uint32_t off = (uint32_t)((brow + nt * 16) * 128 + (kk * 2 + bc16) * 16);
                ldsm_x4(bf4, bT + SWZ(off));
#pragma unroll
                for (int mt = 0; mt < 4; ++mt) {
                    mma_bf16(acc[mt][nt * 2 + 0], af[mt], bf4[0], bf4[1]);
                    mma_bf16(acc[mt][nt * 2 + 1], af[mt], bf4[2], bf4[3]);
                }
            }
        }
        __syncthreads();   // protect buf before chunk ch+2 overwrites it
    }

    // ---- epilogue ----
    const int mrow_lo = warp_m * 64 + (lane >> 2);   // + mt*16 ; +8 for hi half
    const int ncol0   = warp_n * 64 + (lane & 3) * 2;

    if (MODE == 0) {
#pragma unroll
        for (int mt = 0; mt < 4; ++mt) {
#pragma unroll
            for (int nt = 0; nt < 8; ++nt) {
                int m_a = m0 + mrow_lo + mt * 16;
                int nn  = n0 + ncol0 + nt * 8;
                float2 b2 = *(const float2*)(bias + nn);
                __nv_bfloat162 o0 = __floats2bfloat162_rn(acc[mt][nt][0] + b2.x,
                                                          acc[mt][nt][1] + b2.y);
                __nv_bfloat162 o1 = __floats2bfloat162_rn(acc[mt][nt][2] + b2.x,
                                                          acc[mt][nt][3] + b2.y);
                *(__nv_bfloat162*)(g_patchb + (size_t)m_a * DD + nn)       = o0;
                *(__nv_bfloat162*)(g_patchb + (size_t)(m_a + 8) * DD + nn) = o1;
            }
        }
    } else if (MODE == 1) {
        float s = 0.f;
#pragma unroll
        for (int mt = 0; mt < 4; ++mt) {
#pragma unroll
            for (int nt = 0; nt < 8; ++nt) {
                int m_a = m0 + mrow_lo + mt * 16;
                int m_b = m_a + 8;
                int nn  = n0 + ncol0 + nt * 8;
                bool nv0 = nn < NP, nv1 = (nn + 1) < NP;
                if (m_a < NP) {
                    if (nv0 && m_a != nn)     s += __expf(2.0f * acc[mt][nt][0]);
                    if (nv1 && m_a != nn + 1) s += __expf(2.0f * acc[mt][nt][1]);
                }
                if (m_b < NP) {
                    if (nv0 && m_b != nn)     s += __expf(2.0f * acc[mt][nt][2]);
                    if (nv1 && m_b != nn + 1) s += __expf(2.0f * acc[mt][nt][3]);
                }
            }
        }
        if (blockIdx.x > blockIdx.y) s *= 2.0f;   // symmetric off-diagonal tile
        s = warpSum(s);
        if (lane == 0) s_red[wid] = s;
        __syncthreads();
        if (tid == 0) {
            float r = s_red[0] + s_red[1] + s_red[2] + s_red[3];
            atomicAdd(&g_far[blockIdx.z], r);
        }
    } else {
        const int bA    = n0 / NP;                // first batch in this n tile
        const int split = (bA + 1) * NP;
        float s0 = 0.f, s1 = 0.f;
#pragma unroll
        for (int mt = 0; mt < 4; ++mt) {
#pragma unroll
            for (int nt = 0; nt < 8; ++nt) {
                int nn = n0 + ncol0 + nt * 8;     // all 4 regs share this n pair
                float e = __expf(2.0f * acc[mt][nt][0]) + __expf(2.0f * acc[mt][nt][1])
                        + __expf(2.0f * acc[mt][nt][2]) + __expf(2.0f * acc[mt][nt][3]);
                if (nn < split) s0 += e; else s1 += e;
            }
        }
        float r0 = warpSum(s0), r1 = warpSum(s1);
        if (lane == 0) s_red[wid] = r0;
        __syncthreads();
        if (tid == 0) {
            float r = s_red[0] + s_red[1] + s_red[2] + s_red[3];
            atomicAdd(&g_close[bA], r);
        }
        __syncthreads();
        if (lane == 0) s_red[wid] = r1;
        __syncthreads();
        if (tid == 0 && bA + 1 < BD) {
            float r = s_red[0] + s_red[1] + s_red[2] + s_red[3];
            if (r != 0.f) atomicAdd(&g_close[bA + 1], r);
        }
    }
#undef LOAD_CHUNK
}

// ---------------------------------------------------------------------------
// Small kernels
// ---------------------------------------------------------------------------
__global__ void zero_kernel() {
    const int t = threadIdx.x;
    if (t < BD) { g_far[t] = 0.f; g_close[t] = 0.f; }
}

__global__ void finalize_kernel(float* out) {
    const int t = threadIdx.x;  // 64 threads
    float v = logf(g_far[t]) - logf(g_close[t]);
    __shared__ float red[2];
    float s = warpSum(v);
    if ((t & 31) == 0) red[t >> 5] = s;
    __syncthreads();
    if (t == 0) out[0] = (red[0] + red[1]) * (1.0f / (float)BD);
}

// ---------------------------------------------------------------------------
// Launch. Inputs (metadata order): x, conv_w, conv_b, latent. Output: 1 fp32.
// ---------------------------------------------------------------------------
extern "C" void kernel_launch(void* const* d_in, const int* in_sizes, int n_in,
                              void* d_out, int out_size) {
    (void)in_sizes; (void)n_in; (void)out_size;
    const float* x      = (const float*)d_in[0];
    const float* conv_w = (const float*)d_in[1];
    const float* conv_b = (const float*)d_in[2];
    const float* latent = (const float*)d_in[3];
    float* out = (float*)d_out;

    cudaFuncSetAttribute(mma_kernel<0>, cudaFuncAttributeMaxDynamicSharedMemorySize, SMEM_DYN);
    cudaFuncSetAttribute(mma_kernel<1>, cudaFuncAttributeMaxDynamicSharedMemorySize, SMEM_DYN);
    cudaFuncSetAttribute(mma_kernel<2>, cudaFuncAttributeMaxDynamicSharedMemorySize, SMEM_DYN);

    zero_kernel<<<1, 64>>>();
    wconv_kernel<<<576, 256>>>(conv_w);                       // weights -> bf16
    im2col_kernel<<<6912, 256>>>(x);                          // x -> g_xim bf16
    mma_kernel<0><<<dim3(288, 6), 128, SMEM_DYN>>>(conv_b);   // conv GEMM -> g_patchb
    norm_patch_kernel<<<MROWS, 256>>>();                      // -> g_pnb bf16
    norm_latent_kernel<<<LL, 256>>>(latent);                  // -> g_lnb bf16
    mma_kernel<1><<<dim3(5, 5, BD), 128, SMEM_DYN>>>(nullptr);   // far (symmetric)
    mma_kernel<2><<<dim3(288, 8), 128, SMEM_DYN>>>(nullptr);     // close
    finalize_kernel<<<1, 64>>>(out);
}

// round 14
// speedup vs baseline: 1.8531x; 1.8531x over previous
#include <cuda_runtime.h>
#include <cuda_bf16.h>
#include <cstdint>
#include <math.h>

// Problem constants
#define BD 64                 // batch
#define NP 576                // patches per image (24*24)
#define DD 768                // hidden = 3*16*16
#define LL 1024               // latents
#define MROWS (BD * NP)       // 36864 flattened (b, patch) rows

// ---------------------------------------------------------------------------
// Scratch (__device__ globals: allocation-free per harness rules)
// ---------------------------------------------------------------------------
__device__ __align__(16) __nv_bfloat16 g_patchb[(size_t)MROWS * DD]; // conv out bf16
__device__ __align__(16) __nv_bfloat16 g_xim [(size_t)MROWS * DD];   // im2col(x) bf16
__device__ __align__(16) __nv_bfloat16 g_pnb [(size_t)MROWS * DD];   // normalized patches bf16
__device__ __align__(16) __nv_bfloat16 g_lnb [(size_t)LL * DD];      // normalized latent bf16
__device__ __align__(16) __nv_bfloat16 g_wb  [(size_t)DD * DD];      // conv weights bf16
__device__ float g_far[BD];
__device__ float g_close[BD];

// Lower-triangle tile index maps for the 5x5 far tiling (15 tiles, y <= x).
__device__ const signed char c_trix[15] = {0,1,1,2,2,2,3,3,3,3,4,4,4,4,4};
__device__ const signed char c_triy[15] = {0,0,1,0,1,2,0,1,2,3,0,1,2,3,4};

// ---------------------------------------------------------------------------
// Helpers
// ---------------------------------------------------------------------------
__device__ __forceinline__ uint32_t smem_to_u32(const void* smem_ptr) {
    uint32_t addr;
    asm("{ .reg .u64 tmp; cvta.to.shared.u64 tmp, %1; cvt.u32.u64 %0, tmp; }"
        : "=r"(addr) : "l"(smem_ptr));
    return addr;
}

__device__ __forceinline__ float warpSum(float v) {
#pragma unroll
    for (int o = 16; o; o >>= 1) v += __shfl_xor_sync(0xffffffffu, v, o);
    return v;
}

__device__ __forceinline__ void ldsm_x4(uint32_t* d, uint32_t addr) {
    asm volatile("ldmatrix.sync.aligned.m8n8.x4.shared.b16 {%0,%1,%2,%3}, [%4];"
                 : "=r"(d[0]), "=r"(d[1]), "=r"(d[2]), "=r"(d[3]) : "r"(addr));
}

__device__ __forceinline__ void mma_bf16(float* c, const uint32_t* a,
                                         uint32_t b0, uint32_t b1) {
    asm volatile(
        "mma.sync.aligned.m16n8k16.row.col.f32.bf16.bf16.f32 "
        "{%0,%1,%2,%3}, {%4,%5,%6,%7}, {%8,%9}, {%0,%1,%2,%3};"
        : "+f"(c[0]), "+f"(c[1]), "+f"(c[2]), "+f"(c[3])
        : "r"(a[0]), "r"(a[1]), "r"(a[2]), "r"(a[3]), "r"(b0), "r"(b1));
}

__device__ __forceinline__ void cp16(uint32_t saddr, const void* gptr) {
    asm volatile("cp.async.cg.shared.global [%0], [%1], 16;" :: "r"(saddr), "l"(gptr));
}

#define CP_COMMIT() asm volatile("cp.async.commit_group;")

#define SWZ(off) ((off) ^ (((off) >> 3) & 0x70))

// ---------------------------------------------------------------------------
// Pre-pass kernels: bf16 conversions
// ---------------------------------------------------------------------------

// im2col + fp32->bf16: g_xim[(b*576+np)*768 + k], k = c*256 + rr*16 + cc
__global__ __launch_bounds__(256) void im2col_kernel(const float* __restrict__ x) {
    int s = blockIdx.x * 256 + threadIdx.x;
    int row = s / 48;
    int seg = s - row * 48;
    int b   = row / NP;
    int np  = row - b * NP;
    int ph  = np / 24, pw = np - ph * 24;
    int c   = seg >> 4, rr = seg & 15;
    const float4* src = (const float4*)(x + ((size_t)(b * 3 + c) * 384 + ph * 16 + rr) * 384 + pw * 16);
    float4 q0 = src[0], q1 = src[1], q2 = src[2], q3 = src[3];
    __align__(16) __nv_bfloat162 h[8];
    h[0] = __floats2bfloat162_rn(q0.x, q0.y); h[1] = __floats2bfloat162_rn(q0.z, q0.w);
    h[2] = __floats2bfloat162_rn(q1.x, q1.y); h[3] = __floats2bfloat162_rn(q1.z, q1.w);
    h[4] = __floats2bfloat162_rn(q2.x, q2.y); h[5] = __floats2bfloat162_rn(q2.z, q2.w);
    h[6] = __floats2bfloat162_rn(q3.x, q3.y); h[7] = __floats2bfloat162_rn(q3.z, q3.w);
    uint4* dst = (uint4*)(g_xim + (size_t)row * DD + seg * 16);
    dst[0] = ((const uint4*)h)[0];
    dst[1] = ((const uint4*)h)[1];
}

// conv weights fp32 -> bf16 (OIHW flattening == k order); also zeros accums.
__global__ __launch_bounds__(256) void wconv_kernel(const float* __restrict__ w) {
    int i = blockIdx.x * 256 + threadIdx.x;   // 147456 float4s
    if (blockIdx.x == 0 && threadIdx.x < BD) {
        g_far[threadIdx.x] = 0.f;
        g_close[threadIdx.x] = 0.f;
    }
    float4 q = ((const float4*)w)[i];
    __align__(8) __nv_bfloat162 h2[2] = {__floats2bfloat162_rn(q.x, q.y),
                                         __floats2bfloat162_rn(q.z, q.w)};
    ((uint2*)g_wb)[i] = *(const uint2*)h2;
}

// L2-normalize conv output rows (bf16 in, bf16 out). grid = MROWS, 256 thr.
__global__ __launch_bounds__(256) void norm_patch_kernel() {
    const __nv_bfloat16* p = g_patchb + (size_t)blockIdx.x * DD;
    __nv_bfloat16* o = g_pnb + (size_t)blockIdx.x * DD;
    const int tid = threadIdx.x;
    float v0 = __bfloat162float(p[tid]);
    float v1 = __bfloat162float(p[tid + 256]);
    float v2 = __bfloat162float(p[tid + 512]);
    float ss = v0 * v0 + v1 * v1 + v2 * v2;

    __shared__ float red[8];
    __shared__ float s_inv;
    float t = warpSum(ss);
    if ((tid & 31) == 0) red[tid >> 5] = t;
    __syncthreads();
    if (tid < 32) {
        float u = (tid < 8) ? red[tid] : 0.f;
        u = warpSum(u);
        if (tid == 0) s_inv = 1.0f / fmaxf(sqrtf(u), 1e-8f);
    }
    __syncthreads();
    const float inv = s_inv;
    o[tid]       = __float2bfloat16(v0 * inv);
    o[tid + 256] = __float2bfloat16(v1 * inv);
    o[tid + 512] = __float2bfloat16(v2 * inv);
}

// Normalize latent rows (fp32 in, bf16 out). grid = LL, 256 thr.
__global__ __launch_bounds__(256) void norm_latent_kernel(const float* __restrict__ latent) {
    const float* s = latent + (size_t)blockIdx.x * DD;
    __nv_bfloat16* d = g_lnb + (size_t)blockIdx.x * DD;
    const int tid = threadIdx.x;
    float v0 = s[tid], v1 = s[tid + 256], v2 = s[tid + 512];
    float ss = v0 * v0 + v1 * v1 + v2 * v2;

    __shared__ float red[8];
    __shared__ float s_inv;
    float t = warpSum(ss);
    if ((tid & 31) == 0) red[tid >> 5] = t;
    __syncthreads();
    if (tid < 32) {
        float u = (tid < 8) ? red[tid] : 0.f;
        u = warpSum(u);
        if (tid == 0) s_inv = 1.0f / fmaxf(sqrtf(u), 1e-8f);
    }
    __syncthreads();
    const float inv = s_inv;
    d[tid]       = __float2bfloat16(v0 * inv);
    d[tid + 256] = __float2bfloat16(v1 * inv);
    d[tid + 512] = __float2bfloat16(v2 * inv);
}

// ---------------------------------------------------------------------------
// bf16 HMMA GEMM (R10-proven): 128x128 block tile, BK=64, 2-stage cp.async
// double buffer, SW128-swizzled smem + ldmatrix, mma.sync m16n8k16, fused
// epilogue. 8 warps = 4 (m) x 2 (n); warp tile 32(m) x 64(n).
//   MODE 0: conv   A=g_xim (36864), B=g_wb (768)   -> g_patchb (bf16) + bias
//   MODE 1: far    A=B=g_pnb batch slice (576, clamp+mask) -> exp+reduce
//           grid (15, BD): exact lower-triangle tile list (no culled CTAs)
//   MODE 2: close  A=g_lnb (1024),  B=g_pnb (36864) -> exp+reduce (batch split)
// ---------------------------------------------------------------------------
#define NCHUNK 12
#define TILE_B 16384
#define SMEM_DYN (4 * TILE_B)

template<int MODE>
__global__ __launch_bounds__(256)
void mma_kernel(const float* __restrict__ bias) {
    extern __shared__ __align__(1024) unsigned char smem[];
    __shared__ float s_red[8];
    const uint32_t sbase = smem_to_u32(smem);
    const int tid = threadIdx.x, lane = tid & 31, wid = tid >> 5;
    const int warp_m = wid & 3, warp_n = wid >> 2;

    int m0, n0, bx = 0, by = 0, bz = 0;
    const __nv_bfloat16 *Ap, *Bp;
    if (MODE == 0)      { m0 = blockIdx.x * 128; n0 = blockIdx.y * 128; Ap = g_xim; Bp = g_wb; }
    else if (MODE == 1) { bx = c_trix[blockIdx.x]; by = c_triy[blockIdx.x]; bz = blockIdx.y;
                          m0 = bx * 128; n0 = by * 128;
                          Ap = g_pnb + (size_t)bz * NP * DD; Bp = Ap; }
    else                { m0 = blockIdx.y * 128; n0 = blockIdx.x * 128; Ap = g_lnb; Bp = g_pnb; }

    // Per-thread copy plan: 4 x 16B segments for each of A, B per chunk.
    const __nv_bfloat16* gA[4];
    const __nv_bfloat16* gB[4];
    uint32_t swoff[4];
#pragma unroll
    for (int i = 0; i < 4; ++i) {
        int idx = tid + i * 256;
        int rr = idx >> 3, cc = idx & 7;
        uint32_t off = (uint32_t)(rr * 128 + cc * 16);
        swoff[i] = SWZ(off);
        int ra = m0 + rr, rb = n0 + rr;
        if (MODE == 1) {                        // clamp padded rows; masked later
            ra = ra < NP - 1 ? ra : NP - 1;
            rb = rb < NP - 1 ? rb : NP - 1;
        }
        gA[i] = Ap + (size_t)ra * DD + cc * 8;
        gB[i] = Bp + (size_t)rb * DD + cc * 8;
    }

#define LOAD_CHUNK(ch, buf) do {                                        \
        uint32_t _sA = sbase + (uint32_t)(buf) * (2 * TILE_B);          \
        uint32_t _sB = _sA + TILE_B;                                    \
        _Pragma("unroll")                                               \
        for (int i = 0; i < 4; ++i) {                                   \
            cp16(_sA + swoff[i], (const void*)(gA[i] + (ch) * 64));     \
            cp16(_sB + swoff[i], (const void*)(gB[i] + (ch) * 64));     \
        }                                                               \
        CP_COMMIT();                                                    \
    } while (0)

    float acc[2][8][4] = {};

    // ldmatrix lane mappings
    const int arow = warp_m * 32 + (lane & 15);       // + mt*16
    const int ac16 = lane >> 4;                       // k 16B sub-chunk
    const int brow = warp_n * 64 + (lane & 7) + ((lane >> 4) << 3);  // + nt*16
    const int bc16 = (lane >> 3) & 1;

    LOAD_CHUNK(0, 0);

    for (int ch = 0; ch < NCHUNK; ++ch) {
        const int buf = ch & 1;
        if (ch < NCHUNK - 1) {
            LOAD_CHUNK(ch + 1, buf ^ 1);
            asm volatile("cp.async.wait_group 1;");
        } else {
            asm volatile("cp.async.wait_group 0;");
        }
        __syncthreads();

        const uint32_t aT = sbase + (uint32_t)buf * (2 * TILE_B);
        const uint32_t bT = aT + TILE_B;
#pragma unroll
        for (int kk = 0; kk < 4; ++kk) {
            uint32_t af[2][4];
#pragma unroll
            for (int mt = 0; mt < 2; ++mt) {
                uint32_t off = (uint32_t)((arow + mt * 16) * 128 + (kk * 2 + ac16) * 16);
                ldsm_x4(af[mt], aT + SWZ(off));
            }
#pragma unroll
            for (int nt = 0; nt < 4; ++nt) {
                uint32_t bf4[4];
                uint32_t off = (uint32_t)((brow + nt * 16) * 128 + (kk * 2 + bc16) * 16);
                ldsm_x4(bf4, bT + SWZ(off));
#pragma unroll
                for (int mt = 0; mt < 2; ++mt) {
                    mma_bf16(acc[mt][nt * 2 + 0], af[mt], bf4[0], bf4[1]);
                    mma_bf16(acc[mt][nt * 2 + 1], af[mt], bf4[2], bf4[3]);
                }
            }
        }
        __syncthreads();   // protect buf before chunk ch+2 overwrites it
    }

    // ---- epilogue ----
    const int mrow_lo = warp_m * 32 + (lane >> 2);   // + mt*16 ; +8 for hi half
    const int ncol0   = warp_n * 64 + (lane & 3) * 2;

    if (MODE == 0) {
#pragma unroll
        for (int mt = 0; mt < 2; ++mt) {
#pragma unroll
            for (int nt = 0; nt < 8; ++nt) {
                int m_a = m0 + mrow_lo + mt * 16;
                int nn  = n0 + ncol0 + nt * 8;
                float2 b2 = *(const float2*)(bias + nn);
                __nv_bfloat162 o0 = __floats2bfloat162_rn(acc[mt][nt][0] + b2.x,
                                                          acc[mt][nt][1] + b2.y);
                __nv_bfloat162 o1 = __floats2bfloat162_rn(acc[mt][nt][2] + b2.x,
                                                          acc[mt][nt][3] + b2.y);
                *(__nv_bfloat162*)(g_patchb + (size_t)m_a * DD + nn)       = o0;
                *(__nv_bfloat162*)(g_patchb + (size_t)(m_a + 8) * DD + nn) = o1;
            }
        }
    } else if (MODE == 1) {
        float s = 0.f;
#pragma unroll
        for (int mt = 0; mt < 2; ++mt) {
#pragma unroll
            for (int nt = 0; nt < 8; ++nt) {
                int m_a = m0 + mrow_lo + mt * 16;
                int m_b = m_a + 8;
                int nn  = n0 + ncol0 + nt * 8;
                bool nv0 = nn < NP, nv1 = (nn + 1) < NP;
                if (m_a < NP) {
                    if (nv0 && m_a != nn)     s += __expf(2.0f * acc[mt][nt][0]);
                    if (nv1 && m_a != nn + 1) s += __expf(2.0f * acc[mt][nt][1]);
                }
                if (m_b < NP) {
                    if (nv0 && m_b != nn)     s += __expf(2.0f * acc[mt][nt][2]);
                    if (nv1 && m_b != nn + 1) s += __expf(2.0f * acc[mt][nt][3]);
                }
            }
        }
        if (bx > by) s *= 2.0f;                  // symmetric off-diagonal tile
        s = warpSum(s);
        if (lane == 0) s_red[wid] = s;
        __syncthreads();
        if (tid == 0) {
            float r = 0.f;
#pragma unroll
            for (int i = 0; i < 8; ++i) r += s_red[i];
            atomicAdd(&g_far[bz], r);
        }
    } else {
        const int bA    = n0 / NP;                // first batch in this n tile
        const int split = (bA + 1) * NP;
        float s0 = 0.f, s1 = 0.f;
#pragma unroll
        for (int mt = 0; mt < 2; ++mt) {
#pragma unroll
            for (int nt = 0; nt < 8; ++nt) {
                int nn = n0 + ncol0 + nt * 8;     // all 4 regs share this n pair
                float e = __expf(2.0f * acc[mt][nt][0]) + __expf(2.0f * acc[mt][nt][1])
                        + __expf(2.0f * acc[mt][nt][2]) + __expf(2.0f * acc[mt][nt][3]);
                if (nn < split) s0 += e; else s1 += e;
            }
        }
        float r0 = warpSum(s0), r1 = warpSum(s1);
        if (lane == 0) s_red[wid] = r0;
        __syncthreads();
        if (tid == 0) {
            float r = 0.f;
#pragma unroll
            for (int i = 0; i < 8; ++i) r += s_red[i];
            atomicAdd(&g_close[bA], r);
        }
        __syncthreads();
        if (lane == 0) s_red[wid] = r1;
        __syncthreads();
        if (tid == 0 && bA + 1 < BD) {
            float r = 0.f;
#pragma unroll
            for (int i = 0; i < 8; ++i) r += s_red[i];
            if (r != 0.f) atomicAdd(&g_close[bA + 1], r);
        }
    }
#undef LOAD_CHUNK
}

// ---------------------------------------------------------------------------
// Finalize
// ---------------------------------------------------------------------------
__global__ void finalize_kernel(float* out) {
    const int t = threadIdx.x;  // 64 threads
    float v = logf(g_far[t]) - logf(g_close[t]);
    __shared__ float red[2];
    float s = warpSum(v);
    if ((t & 31) == 0) red[t >> 5] = s;
    __syncthreads();
    if (t == 0) out[0] = (red[0] + red[1]) * (1.0f / (float)BD);
}

// ---------------------------------------------------------------------------
// Launch. Inputs (metadata order): x, conv_w, conv_b, latent. Output: 1 fp32.
// ---------------------------------------------------------------------------
extern "C" void kernel_launch(void* const* d_in, const int* in_sizes, int n_in,
                              void* d_out, int out_size) {
    (void)in_sizes; (void)n_in; (void)out_size;
    const float* x      = (const float*)d_in[0];
    const float* conv_w = (const float*)d_in[1];
    const float* conv_b = (const float*)d_in[2];
    const float* latent = (const float*)d_in[3];
    float* out = (float*)d_out;

    cudaFuncSetAttribute(mma_kernel<0>, cudaFuncAttributeMaxDynamicSharedMemorySize, SMEM_DYN);
    cudaFuncSetAttribute(mma_kernel<1>, cudaFuncAttributeMaxDynamicSharedMemorySize, SMEM_DYN);
    cudaFuncSetAttribute(mma_kernel<2>, cudaFuncAttributeMaxDynamicSharedMemorySize, SMEM_DYN);

    wconv_kernel<<<576, 256>>>(conv_w);                       // weights -> bf16 (+ zero accums)
    im2col_kernel<<<6912, 256>>>(x);                          // x -> g_xim bf16
    mma_kernel<0><<<dim3(288, 6), 256, SMEM_DYN>>>(conv_b);   // conv GEMM -> g_patchb
    norm_patch_kernel<<<MROWS, 256>>>();                      // -> g_pnb bf16
    norm_latent_kernel<<<LL, 256>>>(latent);                  // -> g_lnb bf16
    mma_kernel<1><<<dim3(15, BD), 256, SMEM_DYN>>>(nullptr);  // far (exact lower-tri grid)
    mma_kernel<2><<<dim3(288, 8), 256, SMEM_DYN>>>(nullptr);  // close
    finalize_kernel<<<1, 64>>>(out);
}

// round 16
// speedup vs baseline: 1.9673x; 1.0616x over previous
#include <cuda_runtime.h>
#include <cuda_bf16.h>
#include <cstdint>
#include <math.h>

// Problem constants
#define BD 64                 // batch
#define NP 576                // patches per image (24*24)
#define DD 768                // hidden = 3*16*16
#define LL 1024               // latents
#define MROWS (BD * NP)       // 36864 flattened (b, patch) rows

// ---------------------------------------------------------------------------
// Scratch (__device__ globals: allocation-free per harness rules)
// ---------------------------------------------------------------------------
__device__ __align__(16) __nv_bfloat16 g_patchb[(size_t)MROWS * DD]; // conv out bf16
__device__ __align__(16) __nv_bfloat16 g_xim [(size_t)MROWS * DD];   // im2col(x) bf16
__device__ __align__(16) __nv_bfloat16 g_pnb [(size_t)MROWS * DD];   // normalized patches bf16
__device__ __align__(16) __nv_bfloat16 g_lnb [(size_t)LL * DD];      // normalized latent bf16
__device__ __align__(16) __nv_bfloat16 g_wb  [(size_t)DD * DD];      // conv weights bf16
__device__ float g_far[BD];
__device__ float g_close[BD];

// Lower-triangle tile index maps for the 5x5 far tiling (15 tiles, y <= x).
__device__ const signed char c_trix[15] = {0,1,1,2,2,2,3,3,3,3,4,4,4,4,4};
__device__ const signed char c_triy[15] = {0,0,1,0,1,2,0,1,2,3,0,1,2,3,4};

// ---------------------------------------------------------------------------
// Helpers
// ---------------------------------------------------------------------------
__device__ __forceinline__ uint32_t smem_to_u32(const void* smem_ptr) {
    uint32_t addr;
    asm("{ .reg .u64 tmp; cvta.to.shared.u64 tmp, %1; cvt.u32.u64 %0, tmp; }"
        : "=r"(addr) : "l"(smem_ptr));
    return addr;
}

__device__ __forceinline__ float warpSum(float v) {
#pragma unroll
    for (int o = 16; o; o >>= 1) v += __shfl_xor_sync(0xffffffffu, v, o);
    return v;
}

__device__ __forceinline__ void ldsm_x4(uint32_t* d, uint32_t addr) {
    asm volatile("ldmatrix.sync.aligned.m8n8.x4.shared.b16 {%0,%1,%2,%3}, [%4];"
                 : "=r"(d[0]), "=r"(d[1]), "=r"(d[2]), "=r"(d[3]) : "r"(addr));
}

__device__ __forceinline__ void mma_bf16(float* c, const uint32_t* a,
                                         uint32_t b0, uint32_t b1) {
    asm volatile(
        "mma.sync.aligned.m16n8k16.row.col.f32.bf16.bf16.f32 "
        "{%0,%1,%2,%3}, {%4,%5,%6,%7}, {%8,%9}, {%0,%1,%2,%3};"
        : "+f"(c[0]), "+f"(c[1]), "+f"(c[2]), "+f"(c[3])
        : "r"(a[0]), "r"(a[1]), "r"(a[2]), "r"(a[3]), "r"(b0), "r"(b1));
}

__device__ __forceinline__ void cp16(uint32_t saddr, const void* gptr) {
    asm volatile("cp.async.cg.shared.global [%0], [%1], 16;" :: "r"(saddr), "l"(gptr));
}

#define CP_COMMIT() asm volatile("cp.async.commit_group;")

#define SWZ(off) ((off) ^ (((off) >> 3) & 0x70))

// ---------------------------------------------------------------------------
// Pre-pass kernels: bf16 conversions
// ---------------------------------------------------------------------------

// im2col + fp32->bf16: g_xim[(b*576+np)*768 + k], k = c*256 + rr*16 + cc
__global__ __launch_bounds__(256) void im2col_kernel(const float* __restrict__ x) {
    int s = blockIdx.x * 256 + threadIdx.x;
    int row = s / 48;
    int seg = s - row * 48;
    int b   = row / NP;
    int np  = row - b * NP;
    int ph  = np / 24, pw = np - ph * 24;
    int c   = seg >> 4, rr = seg & 15;
    const float4* src = (const float4*)(x + ((size_t)(b * 3 + c) * 384 + ph * 16 + rr) * 384 + pw * 16);
    float4 q0 = src[0], q1 = src[1], q2 = src[2], q3 = src[3];
    __align__(16) __nv_bfloat162 h[8];
    h[0] = __floats2bfloat162_rn(q0.x, q0.y); h[1] = __floats2bfloat162_rn(q0.z, q0.w);
    h[2] = __floats2bfloat162_rn(q1.x, q1.y); h[3] = __floats2bfloat162_rn(q1.z, q1.w);
    h[4] = __floats2bfloat162_rn(q2.x, q2.y); h[5] = __floats2bfloat162_rn(q2.z, q2.w);
    h[6] = __floats2bfloat162_rn(q3.x, q3.y); h[7] = __floats2bfloat162_rn(q3.z, q3.w);
    uint4* dst = (uint4*)(g_xim + (size_t)row * DD + seg * 16);
    dst[0] = ((const uint4*)h)[0];
    dst[1] = ((const uint4*)h)[1];
}

// conv weights fp32 -> bf16 (OIHW flattening == k order); also zeros accums.
__global__ __launch_bounds__(256) void wconv_kernel(const float* __restrict__ w) {
    int i = blockIdx.x * 256 + threadIdx.x;   // 147456 float4s
    if (blockIdx.x == 0 && threadIdx.x < BD) {
        g_far[threadIdx.x] = 0.f;
        g_close[threadIdx.x] = 0.f;
    }
    float4 q = ((const float4*)w)[i];
    __align__(8) __nv_bfloat162 h2[2] = {__floats2bfloat162_rn(q.x, q.y),
                                         __floats2bfloat162_rn(q.z, q.w)};
    ((uint2*)g_wb)[i] = *(const uint2*)h2;
}

// L2-normalize conv rows, warp-per-row (8 rows/block, no smem/barriers).
// grid = MROWS/8 = 4608, 256 thr. Lane reads 3 x uint4 = 24 bf16.
__global__ __launch_bounds__(256) void norm_patch_kernel() {
    const int row  = blockIdx.x * 8 + (threadIdx.x >> 5);
    const int lane = threadIdx.x & 31;
    const uint4* pr = (const uint4*)(g_patchb + (size_t)row * DD);
    uint4*       po = (uint4*)(g_pnb + (size_t)row * DD);

    uint4 v[3];
    float f[3][8];
    float ss = 0.f;
#pragma unroll
    for (int i = 0; i < 3; ++i) {
        v[i] = pr[lane + i * 32];
        const uint32_t* w = (const uint32_t*)&v[i];
#pragma unroll
        for (int j = 0; j < 4; ++j) {
            float2 d = __bfloat1622float2(*(const __nv_bfloat162*)&w[j]);
            f[i][j * 2] = d.x; f[i][j * 2 + 1] = d.y;
            ss += d.x * d.x + d.y * d.y;
        }
    }
    ss = warpSum(ss);
    const float inv = 1.0f / fmaxf(sqrtf(ss), 1e-8f);
#pragma unroll
    for (int i = 0; i < 3; ++i) {
        uint4 o;
        uint32_t* w = (uint32_t*)&o;
#pragma unroll
        for (int j = 0; j < 4; ++j) {
            __nv_bfloat162 h = __floats2bfloat162_rn(f[i][j * 2] * inv,
                                                     f[i][j * 2 + 1] * inv);
            w[j] = *(const uint32_t*)&h;
        }
        po[lane + i * 32] = o;
    }
}

// Normalize latent rows, warp-per-row. grid = LL/8 = 128, 256 thr.
// Lane reads 6 x float4 = 24 fp32, writes 3 x uint2 = 24 bf16.
__global__ __launch_bounds__(256) void norm_latent_kernel(const float* __restrict__ latent) {
    const int row  = blockIdx.x * 8 + (threadIdx.x >> 5);
    const int lane = threadIdx.x & 31;
    const float4* pr = (const float4*)(latent + (size_t)row * DD);
    uint2*        po = (uint2*)(g_lnb + (size_t)row * DD);

    float4 v[6];
    float ss = 0.f;
#pragma unroll
    for (int i = 0; i < 6; ++i) {
        v[i] = pr[lane + i * 32];
        ss += v[i].x * v[i].x + v[i].y * v[i].y + v[i].z * v[i].z + v[i].w * v[i].w;
    }
    ss = warpSum(ss);
    const float inv = 1.0f / fmaxf(sqrtf(ss), 1e-8f);
#pragma unroll
    for (int i = 0; i < 6; ++i) {
        __align__(8) __nv_bfloat162 h[2] = {
            __floats2bfloat162_rn(v[i].x * inv, v[i].y * inv),
            __floats2bfloat162_rn(v[i].z * inv, v[i].w * inv)};
        po[lane + i * 32] = *(const uint2*)h;
    }
}

// ---------------------------------------------------------------------------
// bf16 HMMA GEMM (R10-proven): 128x128 block tile, BK=64, 2-stage cp.async
// double buffer, SW128-swizzled smem + ldmatrix, mma.sync m16n8k16, fused
// epilogue. 8 warps = 4 (m) x 2 (n); warp tile 32(m) x 64(n).
//   MODE 0: conv   A=g_xim (36864), B=g_wb (768)   -> g_patchb (bf16) + bias
//   MODE 1: far    A=B=g_pnb batch slice (576, clamp+mask) -> exp+reduce
//           grid (15, BD): exact lower-triangle tile list (no culled CTAs)
//   MODE 2: close  A=g_lnb (1024),  B=g_pnb (36864) -> exp+reduce (batch split)
// ---------------------------------------------------------------------------
#define NCHUNK 12
#define TILE_B 16384
#define SMEM_DYN (4 * TILE_B)

template<int MODE>
__global__ __launch_bounds__(256)
void mma_kernel(const float* __restrict__ bias) {
    extern __shared__ __align__(1024) unsigned char smem[];
    __shared__ float s_red[8];
    const uint32_t sbase = smem_to_u32(smem);
    const int tid = threadIdx.x, lane = tid & 31, wid = tid >> 5;
    const int warp_m = wid & 3, warp_n = wid >> 2;

    int m0, n0, bx = 0, by = 0, bz = 0;
    const __nv_bfloat16 *Ap, *Bp;
    if (MODE == 0)      { m0 = blockIdx.x * 128; n0 = blockIdx.y * 128; Ap = g_xim; Bp = g_wb; }
    else if (MODE == 1) { bx = c_trix[blockIdx.x]; by = c_triy[blockIdx.x]; bz = blockIdx.y;
                          m0 = bx * 128; n0 = by * 128;
                          Ap = g_pnb + (size_t)bz * NP * DD; Bp = Ap; }
    else                { m0 = blockIdx.y * 128; n0 = blockIdx.x * 128; Ap = g_lnb; Bp = g_pnb; }

    // Per-thread copy plan: 4 x 16B segments for each of A, B per chunk.
    const __nv_bfloat16* gA[4];
    const __nv_bfloat16* gB[4];
    uint32_t swoff[4];
#pragma unroll
    for (int i = 0; i < 4; ++i) {
        int idx = tid + i * 256;
        int rr = idx >> 3, cc = idx & 7;
        uint32_t off = (uint32_t)(rr * 128 + cc * 16);
        swoff[i] = SWZ(off);
        int ra = m0 + rr, rb = n0 + rr;
        if (MODE == 1) {                        // clamp padded rows; masked later
            ra = ra < NP - 1 ? ra : NP - 1;
            rb = rb < NP - 1 ? rb : NP - 1;
        }
        gA[i] = Ap + (size_t)ra * DD + cc * 8;
        gB[i] = Bp + (size_t)rb * DD + cc * 8;
    }

#define LOAD_CHUNK(ch, buf) do {                                        \
        uint32_t _sA = sbase + (uint32_t)(buf) * (2 * TILE_B);          \
        uint32_t _sB = _sA + TILE_B;                                    \
        _Pragma("unroll")                                               \
        for (int i = 0; i < 4; ++i) {                                   \
            cp16(_sA + swoff[i], (const void*)(gA[i] + (ch) * 64));     \
            cp16(_sB + swoff[i], (const void*)(gB[i] + (ch) * 64));     \
        }                                                               \
        CP_COMMIT();                                                    \
    } while (0)

    float acc[2][8][4] = {};

    // ldmatrix lane mappings
    const int arow = warp_m * 32 + (lane & 15);       // + mt*16
    const int ac16 = lane >> 4;                       // k 16B sub-chunk
    const int brow = warp_n * 64 + (lane & 7) + ((lane >> 4) << 3);  // + nt*16
    const int bc16 = (lane >> 3) & 1;

    LOAD_CHUNK(0, 0);

    for (int ch = 0; ch < NCHUNK; ++ch) {
        const int buf = ch & 1;
        if (ch < NCHUNK - 1) {
            LOAD_CHUNK(ch + 1, buf ^ 1);
            asm volatile("cp.async.wait_group 1;");
        } else {
            asm volatile("cp.async.wait_group 0;");
        }
        __syncthreads();

        const uint32_t aT = sbase + (uint32_t)buf * (2 * TILE_B);
        const uint32_t bT = aT + TILE_B;
#pragma unroll
        for (int kk = 0; kk < 4; ++kk) {
            uint32_t af[2][4];
#pragma unroll
            for (int mt = 0; mt < 2; ++mt) {
                uint32_t off = (uint32_t)((arow + mt * 16) * 128 + (kk * 2 + ac16) * 16);
                ldsm_x4(af[mt], aT + SWZ(off));
            }
#pragma unroll
            for (int nt = 0; nt < 4; ++nt) {
                uint32_t bf4[4];
                uint32_t off = (uint32_t)((brow + nt * 16) * 128 + (kk * 2 + bc16) * 16);
                ldsm_x4(bf4, bT + SWZ(off));
#pragma unroll
                for (int mt = 0; mt < 2; ++mt) {
                    mma_bf16(acc[mt][nt * 2 + 0], af[mt], bf4[0], bf4[1]);
                    mma_bf16(acc[mt][nt * 2 + 1], af[mt], bf4[2], bf4[3]);
                }
            }
        }
        __syncthreads();   // protect buf before chunk ch+2 overwrites it
    }

    // ---- epilogue ----
    const int mrow_lo = warp_m * 32 + (lane >> 2);   // + mt*16 ; +8 for hi half
    const int ncol0   = warp_n * 64 + (lane & 3) * 2;

    if (MODE == 0) {
#pragma unroll
        for (int mt = 0; mt < 2; ++mt) {
#pragma unroll
            for (int nt = 0; nt < 8; ++nt) {
                int m_a = m0 + mrow_lo + mt * 16;
                int nn  = n0 + ncol0 + nt * 8;
                float2 b2 = *(const float2*)(bias + nn);
                __nv_bfloat162 o0 = __floats2bfloat162_rn(acc[mt][nt][0] + b2.x,
                                                          acc[mt][nt][1] + b2.y);
                __nv_bfloat162 o1 = __floats2bfloat162_rn(acc[mt][nt][2] + b2.x,
                                                          acc[mt][nt][3] + b2.y);
                *(__nv_bfloat162*)(g_patchb + (size_t)m_a * DD + nn)       = o0;
                *(__nv_bfloat162*)(g_patchb + (size_t)(m_a + 8) * DD + nn) = o1;
            }
        }
    } else if (MODE == 1) {
        float s = 0.f;
#pragma unroll
        for (int mt = 0; mt < 2; ++mt) {
#pragma unroll
            for (int nt = 0; nt < 8; ++nt) {
                int m_a = m0 + mrow_lo + mt * 16;
                int m_b = m_a + 8;
                int nn  = n0 + ncol0 + nt * 8;
                bool nv0 = nn < NP, nv1 = (nn + 1) < NP;
                if (m_a < NP) {
                    if (nv0 && m_a != nn)     s += __expf(2.0f * acc[mt][nt][0]);
                    if (nv1 && m_a != nn + 1) s += __expf(2.0f * acc[mt][nt][1]);
                }
                if (m_b < NP) {
                    if (nv0 && m_b != nn)     s += __expf(2.0f * acc[mt][nt][2]);
                    if (nv1 && m_b != nn + 1) s += __expf(2.0f * acc[mt][nt][3]);
                }
            }
        }
        if (bx > by) s *= 2.0f;                  // symmetric off-diagonal tile
        s = warpSum(s);
        if (lane == 0) s_red[wid] = s;
        __syncthreads();
        if (tid == 0) {
            float r = 0.f;
#pragma unroll
            for (int i = 0; i < 8; ++i) r += s_red[i];
            atomicAdd(&g_far[bz], r);
        }
    } else {
        const int bA    = n0 / NP;                // first batch in this n tile
        const int split = (bA + 1) * NP;
        float s0 = 0.f, s1 = 0.f;
#pragma unroll
        for (int mt = 0; mt < 2; ++mt) {
#pragma unroll
            for (int nt = 0; nt < 8; ++nt) {
                int nn = n0 + ncol0 + nt * 8;     // all 4 regs share this n pair
                float e = __expf(2.0f * acc[mt][nt][0]) + __expf(2.0f * acc[mt][nt][1])
                        + __expf(2.0f * acc[mt][nt][2]) + __expf(2.0f * acc[mt][nt][3]);
                if (nn < split) s0 += e; else s1 += e;
            }
        }
        float r0 = warpSum(s0), r1 = warpSum(s1);
        if (lane == 0) s_red[wid] = r0;
        __syncthreads();
        if (tid == 0) {
            float r = 0.f;
#pragma unroll
            for (int i = 0; i < 8; ++i) r += s_red[i];
            atomicAdd(&g_close[bA], r);
        }
        __syncthreads();
        if (lane == 0) s_red[wid] = r1;
        __syncthreads();
        if (tid == 0 && bA + 1 < BD) {
            float r = 0.f;
#pragma unroll
            for (int i = 0; i < 8; ++i) r += s_red[i];
            if (r != 0.f) atomicAdd(&g_close[bA + 1], r);
        }
    }
#undef LOAD_CHUNK
}

// ---------------------------------------------------------------------------
// Finalize
// ---------------------------------------------------------------------------
__global__ void finalize_kernel(float* out) {
    const int t = threadIdx.x;  // 64 threads
    float v = logf(g_far[t]) - logf(g_close[t]);
    __shared__ float red[2];
    float s = warpSum(v);
    if ((t & 31) == 0) red[t >> 5] = s;
    __syncthreads();
    if (t == 0) out[0] = (red[0] + red[1]) * (1.0f / (float)BD);
}

// ---------------------------------------------------------------------------
// Launch. Inputs (metadata order): x, conv_w, conv_b, latent. Output: 1 fp32.
// ---------------------------------------------------------------------------
extern "C" void kernel_launch(void* const* d_in, const int* in_sizes, int n_in,
                              void* d_out, int out_size) {
    (void)in_sizes; (void)n_in; (void)out_size;
    const float* x      = (const float*)d_in[0];
    const float* conv_w = (const float*)d_in[1];
    const float* conv_b = (const float*)d_in[2];
    const float* latent = (const float*)d_in[3];
    float* out = (float*)d_out;

    cudaFuncSetAttribute(mma_kernel<0>, cudaFuncAttributeMaxDynamicSharedMemorySize, SMEM_DYN);
    cudaFuncSetAttribute(mma_kernel<1>, cudaFuncAttributeMaxDynamicSharedMemorySize, SMEM_DYN);
    cudaFuncSetAttribute(mma_kernel<2>, cudaFuncAttributeMaxDynamicSharedMemorySize, SMEM_DYN);

    wconv_kernel<<<576, 256>>>(conv_w);                       // weights -> bf16 (+ zero accums)
    im2col_kernel<<<6912, 256>>>(x);                          // x -> g_xim bf16
    mma_kernel<0><<<dim3(288, 6), 256, SMEM_DYN>>>(conv_b);   // conv GEMM -> g_patchb
    norm_patch_kernel<<<MROWS / 8, 256>>>();                  // warp-per-row -> g_pnb
    norm_latent_kernel<<<LL / 8, 256>>>(latent);              // warp-per-row -> g_lnb
    mma_kernel<1><<<dim3(15, BD), 256, SMEM_DYN>>>(nullptr);  // far (exact lower-tri grid)
    mma_kernel<2><<<dim3(288, 8), 256, SMEM_DYN>>>(nullptr);  // close
    finalize_kernel<<<1, 64>>>(out);
}